// round 5
// baseline (speedup 1.0000x reference)
#include <cuda_runtime.h>
#include <math.h>

// ---------------------------------------------------------------------------
// helpers
// ---------------------------------------------------------------------------
__device__ __forceinline__ float2 cmul(float2 a, float2 b) {
    return make_float2(a.x * b.x - a.y * b.y, a.x * b.y + a.y * b.x);
}
__device__ __forceinline__ float ftanh(float x) {
    float r; asm("tanh.approx.f32 %0, %1;" : "=f"(r) : "f"(x)); return r;
}
__device__ __forceinline__ float fsig(float x) {          // sigmoid via HW tanh
    return fmaf(0.5f, ftanh(0.5f * x), 0.5f);
}

// ---------------------------------------------------------------------------
// Kernel A: QCNN. Circuit factorizes over qubit pairs; Z_7 depends only on the
// (6,7) subsystem -> 4-amplitude sim. Params: w[9:12] (conv), w[21:24] (pool).
// Fast MUFU sincos (args in [0, 2pi] / small).
// ---------------------------------------------------------------------------
__global__ void qcnn_kernel(const float* __restrict__ x,
                            const float* __restrict__ w,
                            float* __restrict__ out) {
    int i = blockIdx.x * blockDim.x + threadIdx.x;
    if (i >= 2048) return;

    float2 q6a0, q6a1, q7a0, q7a1;
    {
        float ph = 2.0f * x[i * 8 + 6];
        float sp, cp; __sincosf(ph, &sp, &cp);
        q6a0 = make_float2(0.5f * (1.0f + cp), 0.5f * sp);
        float2 t = make_float2(0.5f * (1.0f - cp), -0.5f * sp);
        q6a1 = make_float2(cp * t.x - sp * t.y, cp * t.y + sp * t.x);
    }
    {
        float ph = 2.0f * x[i * 8 + 7];
        float sp, cp; __sincosf(ph, &sp, &cp);
        q7a0 = make_float2(0.5f * (1.0f + cp), 0.5f * sp);
        float2 t = make_float2(0.5f * (1.0f - cp), -0.5f * sp);
        q7a1 = make_float2(cp * t.x - sp * t.y, cp * t.y + sp * t.x);
    }

    float2 s00 = cmul(q6a0, q7a0);
    float2 s01 = cmul(q6a0, q7a1);
    float2 s10 = cmul(q6a1, q7a0);
    float2 s11 = cmul(q6a1, q7a1);

    const float R = 0.70710678118654752f;
    const float2 ePp = make_float2(R,  R);   // e^{+i pi/4}
    const float2 ePm = make_float2(R, -R);   // e^{-i pi/4}

    float w9 = w[9], w10 = w[10], w11 = w[11];
    float w21 = w[21], w22 = w[22], w23 = w[23];

    // ---- conv_block(w[9:12], q1=6, q2=7) ----
    s00 = cmul(s00, ePp); s10 = cmul(s10, ePp);
    s01 = cmul(s01, ePm); s11 = cmul(s11, ePm);
    { float2 t = s01; s01 = s11; s11 = t; }           // CX(7,6)
    {
        float hs, hc; __sincosf(0.5f * w9, &hs, &hc); // RZ(w9) q6
        float2 em = make_float2(hc, -hs), ep = make_float2(hc, hs);
        s00 = cmul(s00, em); s01 = cmul(s01, em);
        s10 = cmul(s10, ep); s11 = cmul(s11, ep);
    }
    {
        float hs, hc; __sincosf(0.5f * w10, &hs, &hc); // RY(w10) q7
        float2 u = s00, v = s01;
        s00 = make_float2(hc * u.x - hs * v.x, hc * u.y - hs * v.y);
        s01 = make_float2(hs * u.x + hc * v.x, hs * u.y + hc * v.y);
        u = s10; v = s11;
        s10 = make_float2(hc * u.x - hs * v.x, hc * u.y - hs * v.y);
        s11 = make_float2(hs * u.x + hc * v.x, hs * u.y + hc * v.y);
    }
    { float2 t = s10; s10 = s11; s11 = t; }           // CX(6,7)
    {
        float hs, hc; __sincosf(0.5f * w11, &hs, &hc); // RY(w11) q7
        float2 u = s00, v = s01;
        s00 = make_float2(hc * u.x - hs * v.x, hc * u.y - hs * v.y);
        s01 = make_float2(hs * u.x + hc * v.x, hs * u.y + hc * v.y);
        u = s10; v = s11;
        s10 = make_float2(hc * u.x - hs * v.x, hc * u.y - hs * v.y);
        s11 = make_float2(hs * u.x + hc * v.x, hs * u.y + hc * v.y);
    }
    { float2 t = s01; s01 = s11; s11 = t; }           // CX(7,6)
    s00 = cmul(s00, ePm); s01 = cmul(s01, ePm);       // RZ(pi/2) q6
    s10 = cmul(s10, ePp); s11 = cmul(s11, ePp);

    // ---- pool_block(w[21:24], src=6, sink=7) ----
    s00 = cmul(s00, ePp); s10 = cmul(s10, ePp);
    s01 = cmul(s01, ePm); s11 = cmul(s11, ePm);
    { float2 t = s01; s01 = s11; s11 = t; }           // CX(7,6)
    {
        float hs, hc; __sincosf(0.5f * w21, &hs, &hc); // RZ(w21) q6
        float2 em = make_float2(hc, -hs), ep = make_float2(hc, hs);
        s00 = cmul(s00, em); s01 = cmul(s01, em);
        s10 = cmul(s10, ep); s11 = cmul(s11, ep);
    }
    {
        float hs, hc; __sincosf(0.5f * w22, &hs, &hc); // RY(w22) q7
        float2 u = s00, v = s01;
        s00 = make_float2(hc * u.x - hs * v.x, hc * u.y - hs * v.y);
        s01 = make_float2(hs * u.x + hc * v.x, hs * u.y + hc * v.y);
        u = s10; v = s11;
        s10 = make_float2(hc * u.x - hs * v.x, hc * u.y - hs * v.y);
        s11 = make_float2(hs * u.x + hc * v.x, hs * u.y + hc * v.y);
    }
    { float2 t = s10; s10 = s11; s11 = t; }           // CX(6,7)
    {
        float hs, hc; __sincosf(0.5f * w23, &hs, &hc); // RY(w23) q7
        float2 u = s00, v = s01;
        s00 = make_float2(hc * u.x - hs * v.x, hc * u.y - hs * v.y);
        s01 = make_float2(hs * u.x + hc * v.x, hs * u.y + hc * v.y);
        u = s10; v = s11;
        s10 = make_float2(hc * u.x - hs * v.x, hc * u.y - hs * v.y);
        s11 = make_float2(hs * u.x + hc * v.x, hs * u.y + hc * v.y);
    }

    float z = (s00.x * s00.x + s00.y * s00.y) + (s10.x * s10.x + s10.y * s10.y)
            - (s01.x * s01.x + s01.y * s01.y) - (s11.x * s11.x + s11.y * s11.y);
    out[i] = z;
}

// ---------------------------------------------------------------------------
// Kernel B: QLSTM, warp-synchronous. Closed form:
//   c_i = cos(v_i + theta_i); qgate = [c1c2c3, c0c1, c0c1c2, c0c1c2c3].
// 64 threads; thread t: batch b = t>>2, gate g = t&3 (4-lane groups in-warp).
// One-shot rotated transpose: round r in {1,2,3}: publish z[(g-r)&3], read from
// lane base+((g+r)&3); received value = gate ((g+r)&3)'s z[g]. 3 independent
// shuffles (single latency layer) instead of 2 dependent butterfly rounds.
// Activations via HW tanh.approx (1 MUFU each).
// ---------------------------------------------------------------------------
__global__ void lstm_kernel(const float* __restrict__ qcnn,   // (B=16, S=128)
                            const float* __restrict__ thf, const float* __restrict__ thi,
                            const float* __restrict__ thg, const float* __restrict__ tho,
                            const float* __restrict__ Wf, const float* __restrict__ bf,
                            const float* __restrict__ Wi, const float* __restrict__ bi,
                            const float* __restrict__ Wg, const float* __restrict__ bg,
                            const float* __restrict__ Wo, const float* __restrict__ bo,
                            const float* __restrict__ Wh, const float* __restrict__ bh,
                            float* __restrict__ out_logits) {
    const unsigned FULL = 0xffffffffu;

    int t = threadIdx.x;             // 0..63
    int b = t >> 2;
    int g = t & 3;
    int lane = t & 31;
    int base = lane & ~3;

    // loop-invariant shuffle source lanes
    int sl1 = base + ((g + 1) & 3);
    int sl2 = base + ((g + 2) & 3);
    int sl3 = base + ((g + 3) & 3);

    const float* Wsel = (g == 0) ? Wf : (g == 1) ? Wi : (g == 2) ? Wg : Wo;
    const float* bsel = (g == 0) ? bf : (g == 1) ? bi : (g == 2) ? bg : bo;
    const float* tsel = (g == 0) ? thf : (g == 1) ? thi : (g == 2) ? thg : tho;

    float W[20], bb[4];
#pragma unroll
    for (int k = 0; k < 20; k++) W[k] = Wsel[k];
#pragma unroll
    for (int k = 0; k < 4; k++) bb[k] = bsel[k] + tsel[k];  // fold theta into bias

    float h0 = 0.f, h1 = 0.f, h2 = 0.f, h3 = 0.f;
    float cm = 0.f;                                   // c[b][g]

    const float* xp = qcnn + b * 128;
    float x0 = xp[0];
    // x-term of each row, hoisted off the h-dependent path
    float p0 = fmaf(W[0],  x0, bb[0]);
    float p1 = fmaf(W[5],  x0, bb[1]);
    float p2 = fmaf(W[10], x0, bb[2]);
    float p3 = fmaf(W[15], x0, bb[3]);

#pragma unroll 4
    for (int s = 0; s < 128; s++) {
        float xn = xp[(s < 127) ? (s + 1) : 127];     // prefetch next x

        // v_r = p_r + W[r][1..4] . h   (balanced tree, depth ~12 from h)
        float ci0, ci1, ci2, ci3;
        {
            float m0 = W[2]  * h1, m1 = W[7]  * h1, m2 = W[12] * h1, m3 = W[17] * h1;
            float q0 = fmaf(W[1],  h0, p0), q1 = fmaf(W[6],  h0, p1);
            float q2 = fmaf(W[11], h0, p2), q3 = fmaf(W[16], h0, p3);
            float u0 = fmaf(W[3],  h2, m0), u1 = fmaf(W[8],  h2, m1);
            float u2 = fmaf(W[13], h2, m2), u3 = fmaf(W[18], h2, m3);
            ci0 = __cosf(fmaf(W[4],  h3, q0) + u0);
            ci1 = __cosf(fmaf(W[9],  h3, q1) + u1);
            ci2 = __cosf(fmaf(W[14], h3, q2) + u2);
            ci3 = __cosf(fmaf(W[19], h3, q3) + u3);
        }

        // my gate's qgate outputs
        float c23 = ci2 * ci3;
        float z1  = ci0 * ci1;
        float z0  = ci1 * c23;
        float z2  = z1 * ci2;
        float z3  = z1 * c23;

        // publish z[(g-r)&3] for r=1,2,3 (loop-invariant predicates -> FSEL)
        float pub1 = (g == 0) ? z3 : (g == 1) ? z0 : (g == 2) ? z1 : z2;
        float pub2 = (g == 0) ? z2 : (g == 1) ? z3 : (g == 2) ? z0 : z1;
        float pub3 = (g == 0) ? z1 : (g == 1) ? z2 : (g == 2) ? z3 : z0;
        float zg   = (g == 0) ? z0 : (g == 1) ? z1 : (g == 2) ? z2 : z3;

        float r1 = __shfl_sync(FULL, pub1, sl1);  // gate (g+1)&3's z[g]
        float r2 = __shfl_sync(FULL, pub2, sl2);  // gate (g+2)&3's z[g]
        float r3 = __shfl_sync(FULL, pub3, sl3);  // gate (g+3)&3's z[g]

        // a_k = gate k's z[g]
        float a0 = (g == 0) ? zg : (g == 3) ? r1 : (g == 2) ? r2 : r3;
        float a1 = (g == 1) ? zg : (g == 0) ? r1 : (g == 3) ? r2 : r3;
        float a2 = (g == 2) ? zg : (g == 1) ? r1 : (g == 0) ? r2 : r3;
        float a3 = (g == 3) ? zg : (g == 2) ? r1 : (g == 1) ? r2 : r3;

        // f = sig(a0), i = sig(a1), g~ = tanh(a2), o = sig(a3)  (HW tanh)
        float fv = fsig(a0);
        float iv = fsig(a1);
        float gv = ftanh(a2);
        float ov = fsig(a3);

        float cn = fmaf(fv, cm, iv * gv);
        cm = cn;
        float hm = ov * ftanh(cn);

        // broadcast h within the 4-lane group
        h0 = __shfl_sync(FULL, hm, base + 0);
        h1 = __shfl_sync(FULL, hm, base + 1);
        h2 = __shfl_sync(FULL, hm, base + 2);
        h3 = __shfl_sync(FULL, hm, base + 3);

        x0 = xn;
        p0 = fmaf(W[0],  x0, bb[0]);
        p1 = fmaf(W[5],  x0, bb[1]);
        p2 = fmaf(W[10], x0, bb[2]);
        p3 = fmaf(W[15], x0, bb[3]);
    }

    if (g == 0) {
        float l = bh[0];
        l = fmaf(Wh[0], h0, l);
        l = fmaf(Wh[1], h1, l);
        l = fmaf(Wh[2], h2, l);
        l = fmaf(Wh[3], h3, l);
        out_logits[b] = l;
    }
}

// ---------------------------------------------------------------------------
// Launch
// ---------------------------------------------------------------------------
extern "C" void kernel_launch(void* const* d_in, const int* in_sizes, int n_in,
                              void* d_out, int out_size) {
    const float* x   = (const float*)d_in[0];   // (16,128,8)
    const float* qw  = (const float*)d_in[1];   // (42,)
    const float* thf = (const float*)d_in[2];
    const float* thi = (const float*)d_in[3];
    const float* thg = (const float*)d_in[4];
    const float* tho = (const float*)d_in[5];
    const float* Wf  = (const float*)d_in[6];
    const float* bf  = (const float*)d_in[7];
    const float* Wi  = (const float*)d_in[8];
    const float* bi  = (const float*)d_in[9];
    const float* Wg  = (const float*)d_in[10];
    const float* bg  = (const float*)d_in[11];
    const float* Wo  = (const float*)d_in[12];
    const float* bo  = (const float*)d_in[13];
    const float* Wh  = (const float*)d_in[14];
    const float* bh  = (const float*)d_in[15];

    float* out = (float*)d_out;   // [0:2048] qcnn_out, [2048:2064] logits

    qcnn_kernel<<<16, 128>>>(x, qw, out);
    lstm_kernel<<<1, 64>>>(out, thf, thi, thg, tho,
                           Wf, bf, Wi, bi, Wg, bg, Wo, bo, Wh, bh,
                           out + 2048);
}

// round 7
// speedup vs baseline: 1.6764x; 1.6764x over previous
#include <cuda_runtime.h>
#include <math.h>

// ---------------------------------------------------------------------------
// helpers
// ---------------------------------------------------------------------------
__device__ __forceinline__ float2 cmul(float2 a, float2 b) {
    return make_float2(a.x * b.x - a.y * b.y, a.x * b.y + a.y * b.x);
}
__device__ __forceinline__ float ftanh(float x) {
    float r; asm("tanh.approx.f32 %0, %1;" : "=f"(r) : "f"(x)); return r;
}
__device__ __forceinline__ float fsig(float x) {          // sigmoid via HW tanh
    return fmaf(0.5f, ftanh(0.5f * x), 0.5f);
}

// ---------------------------------------------------------------------------
// Kernel A: QCNN. Circuit factorizes over qubit pairs; Z_7 depends only on the
// (6,7) subsystem -> 4-amplitude sim. Params: w[9:12] (conv), w[21:24] (pool).
// ---------------------------------------------------------------------------
__global__ void qcnn_kernel(const float* __restrict__ x,
                            const float* __restrict__ w,
                            float* __restrict__ out) {
    int i = blockIdx.x * blockDim.x + threadIdx.x;
    if (i >= 2048) return;

    float2 q6a0, q6a1, q7a0, q7a1;
    {
        float ph = 2.0f * x[i * 8 + 6];
        float sp, cp; __sincosf(ph, &sp, &cp);
        q6a0 = make_float2(0.5f * (1.0f + cp), 0.5f * sp);
        float2 t = make_float2(0.5f * (1.0f - cp), -0.5f * sp);
        q6a1 = make_float2(cp * t.x - sp * t.y, cp * t.y + sp * t.x);
    }
    {
        float ph = 2.0f * x[i * 8 + 7];
        float sp, cp; __sincosf(ph, &sp, &cp);
        q7a0 = make_float2(0.5f * (1.0f + cp), 0.5f * sp);
        float2 t = make_float2(0.5f * (1.0f - cp), -0.5f * sp);
        q7a1 = make_float2(cp * t.x - sp * t.y, cp * t.y + sp * t.x);
    }

    float2 s00 = cmul(q6a0, q7a0);
    float2 s01 = cmul(q6a0, q7a1);
    float2 s10 = cmul(q6a1, q7a0);
    float2 s11 = cmul(q6a1, q7a1);

    const float R = 0.70710678118654752f;
    const float2 ePp = make_float2(R,  R);   // e^{+i pi/4}
    const float2 ePm = make_float2(R, -R);   // e^{-i pi/4}

    float w9 = w[9], w10 = w[10], w11 = w[11];
    float w21 = w[21], w22 = w[22], w23 = w[23];

    // ---- conv_block(w[9:12], q1=6, q2=7) ----
    s00 = cmul(s00, ePp); s10 = cmul(s10, ePp);
    s01 = cmul(s01, ePm); s11 = cmul(s11, ePm);
    { float2 t = s01; s01 = s11; s11 = t; }           // CX(7,6)
    {
        float hs, hc; __sincosf(0.5f * w9, &hs, &hc); // RZ(w9) q6
        float2 em = make_float2(hc, -hs), ep = make_float2(hc, hs);
        s00 = cmul(s00, em); s01 = cmul(s01, em);
        s10 = cmul(s10, ep); s11 = cmul(s11, ep);
    }
    {
        float hs, hc; __sincosf(0.5f * w10, &hs, &hc); // RY(w10) q7
        float2 u = s00, v = s01;
        s00 = make_float2(hc * u.x - hs * v.x, hc * u.y - hs * v.y);
        s01 = make_float2(hs * u.x + hc * v.x, hs * u.y + hc * v.y);
        u = s10; v = s11;
        s10 = make_float2(hc * u.x - hs * v.x, hc * u.y - hs * v.y);
        s11 = make_float2(hs * u.x + hc * v.x, hs * u.y + hc * v.y);
    }
    { float2 t = s10; s10 = s11; s11 = t; }           // CX(6,7)
    {
        float hs, hc; __sincosf(0.5f * w11, &hs, &hc); // RY(w11) q7
        float2 u = s00, v = s01;
        s00 = make_float2(hc * u.x - hs * v.x, hc * u.y - hs * v.y);
        s01 = make_float2(hs * u.x + hc * v.x, hs * u.y + hc * v.y);
        u = s10; v = s11;
        s10 = make_float2(hc * u.x - hs * v.x, hc * u.y - hs * v.y);
        s11 = make_float2(hs * u.x + hc * v.x, hs * u.y + hc * v.y);
    }
    { float2 t = s01; s01 = s11; s11 = t; }           // CX(7,6)
    s00 = cmul(s00, ePm); s01 = cmul(s01, ePm);       // RZ(pi/2) q6
    s10 = cmul(s10, ePp); s11 = cmul(s11, ePp);

    // ---- pool_block(w[21:24], src=6, sink=7) ----
    s00 = cmul(s00, ePp); s10 = cmul(s10, ePp);
    s01 = cmul(s01, ePm); s11 = cmul(s11, ePm);
    { float2 t = s01; s01 = s11; s11 = t; }           // CX(7,6)
    {
        float hs, hc; __sincosf(0.5f * w21, &hs, &hc); // RZ(w21) q6
        float2 em = make_float2(hc, -hs), ep = make_float2(hc, hs);
        s00 = cmul(s00, em); s01 = cmul(s01, em);
        s10 = cmul(s10, ep); s11 = cmul(s11, ep);
    }
    {
        float hs, hc; __sincosf(0.5f * w22, &hs, &hc); // RY(w22) q7
        float2 u = s00, v = s01;
        s00 = make_float2(hc * u.x - hs * v.x, hc * u.y - hs * v.y);
        s01 = make_float2(hs * u.x + hc * v.x, hs * u.y + hc * v.y);
        u = s10; v = s11;
        s10 = make_float2(hc * u.x - hs * v.x, hc * u.y - hs * v.y);
        s11 = make_float2(hs * u.x + hc * v.x, hs * u.y + hc * v.y);
    }
    { float2 t = s10; s10 = s11; s11 = t; }           // CX(6,7)
    {
        float hs, hc; __sincosf(0.5f * w23, &hs, &hc); // RY(w23) q7
        float2 u = s00, v = s01;
        s00 = make_float2(hc * u.x - hs * v.x, hc * u.y - hs * v.y);
        s01 = make_float2(hs * u.x + hc * v.x, hs * u.y + hc * v.y);
        u = s10; v = s11;
        s10 = make_float2(hc * u.x - hs * v.x, hc * u.y - hs * v.y);
        s11 = make_float2(hs * u.x + hc * v.x, hs * u.y + hc * v.y);
    }

    float z = (s00.x * s00.x + s00.y * s00.y) + (s10.x * s10.x + s10.y * s10.y)
            - (s01.x * s01.x + s01.y * s01.y) - (s11.x * s11.x + s11.y * s11.y);
    out[i] = z;
}

// ---------------------------------------------------------------------------
// Kernel B: QLSTM, warp-synchronous. Closed form:
//   c_i = cos(v_i + theta_i); qgate = [c1c2c3, c0c1, c0c1c2, c0c1c2c3].
// 64 threads; thread t: batch b = t>>2, gate g = t&3 (4-lane groups in-warp).
// One-shot rotated transpose (publish z[(g-r)&3], read lane base+((g+r)&3));
// all lane-dependent selects written as balanced depth-2 (g&1)/(g&2) trees.
// ---------------------------------------------------------------------------
__global__ void lstm_kernel(const float* __restrict__ qcnn,   // (B=16, S=128)
                            const float* __restrict__ thf, const float* __restrict__ thi,
                            const float* __restrict__ thg, const float* __restrict__ tho,
                            const float* __restrict__ Wf, const float* __restrict__ bf,
                            const float* __restrict__ Wi, const float* __restrict__ bi,
                            const float* __restrict__ Wg, const float* __restrict__ bg,
                            const float* __restrict__ Wo, const float* __restrict__ bo,
                            const float* __restrict__ Wh, const float* __restrict__ bh,
                            float* __restrict__ out_logits) {
    const unsigned FULL = 0xffffffffu;

    int t = threadIdx.x;             // 0..63
    int b = t >> 2;
    int g = t & 3;
    int lane = t & 31;
    int base = lane & ~3;
    bool g1 = (g & 1) != 0;
    bool g2 = (g & 2) != 0;

    // loop-invariant shuffle source lanes
    int sl1 = base + ((g + 1) & 3);
    int sl2 = base + ((g + 2) & 3);
    int sl3 = base + ((g + 3) & 3);

    const float* Wsel = (g == 0) ? Wf : (g == 1) ? Wi : (g == 2) ? Wg : Wo;
    const float* bsel = (g == 0) ? bf : (g == 1) ? bi : (g == 2) ? bg : bo;
    const float* tsel = (g == 0) ? thf : (g == 1) ? thi : (g == 2) ? thg : tho;

    float W[20], bb[4];
#pragma unroll
    for (int k = 0; k < 20; k++) W[k] = Wsel[k];
#pragma unroll
    for (int k = 0; k < 4; k++) bb[k] = bsel[k] + tsel[k];  // fold theta into bias

    float h0 = 0.f, h1 = 0.f, h2 = 0.f, h3 = 0.f;
    float cm = 0.f;                                   // c[b][g]

    const float* xp = qcnn + b * 128;
    float x0 = xp[0];
    // x-term of each row, hoisted off the h-dependent path
    float p0 = fmaf(W[0],  x0, bb[0]);
    float p1 = fmaf(W[5],  x0, bb[1]);
    float p2 = fmaf(W[10], x0, bb[2]);
    float p3 = fmaf(W[15], x0, bb[3]);

#pragma unroll 2
    for (int s = 0; s < 128; s++) {
        float xn = xp[(s < 127) ? (s + 1) : 127];     // prefetch next x

        // v_r = p_r + W[r][1..4] . h
        float ci0, ci1, ci2, ci3;
        {
            float m0 = W[2]  * h1, m1 = W[7]  * h1, m2 = W[12] * h1, m3 = W[17] * h1;
            float q0 = fmaf(W[1],  h0, p0), q1 = fmaf(W[6],  h0, p1);
            float q2 = fmaf(W[11], h0, p2), q3 = fmaf(W[16], h0, p3);
            float u0 = fmaf(W[3],  h2, m0), u1 = fmaf(W[8],  h2, m1);
            float u2 = fmaf(W[13], h2, m2), u3 = fmaf(W[18], h2, m3);
            ci0 = __cosf(fmaf(W[4],  h3, q0) + u0);
            ci1 = __cosf(fmaf(W[9],  h3, q1) + u1);
            ci2 = __cosf(fmaf(W[14], h3, q2) + u2);
            ci3 = __cosf(fmaf(W[19], h3, q3) + u3);
        }

        // my gate's qgate outputs
        float c23 = ci2 * ci3;
        float z1  = ci0 * ci1;
        float z0  = ci1 * c23;
        float z2  = z1 * ci2;
        float z3  = z1 * c23;

        // balanced depth-2 selects: pub_r = z[(g-r)&3], zg = z[g]
        // pub1: g=0->z3 1->z0 2->z1 3->z2
        float pub1 = g2 ? (g1 ? z2 : z1) : (g1 ? z0 : z3);
        // pub2: g=0->z2 1->z3 2->z0 3->z1
        float pub2 = g2 ? (g1 ? z1 : z0) : (g1 ? z3 : z2);
        // pub3: g=0->z1 1->z2 2->z3 3->z0
        float pub3 = g2 ? (g1 ? z0 : z3) : (g1 ? z2 : z1);
        // zg:   g=0->z0 1->z1 2->z2 3->z3
        float zg   = g2 ? (g1 ? z3 : z2) : (g1 ? z1 : z0);

        float r1 = __shfl_sync(FULL, pub1, sl1);  // gate (g+1)&3's z[g]
        float r2 = __shfl_sync(FULL, pub2, sl2);  // gate (g+2)&3's z[g]
        float r3 = __shfl_sync(FULL, pub3, sl3);  // gate (g+3)&3's z[g]

        // a_k = gate k's z[g]; source index r = (k-g)&3 (0 -> zg)
        // a0: g=0->zg 1->r3 2->r2 3->r1
        float a0 = g2 ? (g1 ? r1 : r2) : (g1 ? r3 : zg);
        // a1: g=0->r1 1->zg 2->r3 3->r2
        float a1 = g2 ? (g1 ? r2 : r3) : (g1 ? zg : r1);
        // a2: g=0->r2 1->r1 2->zg 3->r3
        float a2 = g2 ? (g1 ? r3 : zg) : (g1 ? r1 : r2);
        // a3: g=0->r3 1->r2 2->r1 3->zg
        float a3 = g2 ? (g1 ? zg : r1) : (g1 ? r2 : r3);

        // f,i,g~ first (feed cn), o after
        float fv = fsig(a0);
        float iv = fsig(a1);
        float gv = ftanh(a2);
        float ov = fsig(a3);

        float cn = fmaf(fv, cm, iv * gv);
        cm = cn;
        float hm = ov * ftanh(cn);

        // broadcast h within the 4-lane group
        h0 = __shfl_sync(FULL, hm, base + 0);
        h1 = __shfl_sync(FULL, hm, base + 1);
        h2 = __shfl_sync(FULL, hm, base + 2);
        h3 = __shfl_sync(FULL, hm, base + 3);

        x0 = xn;
        p0 = fmaf(W[0],  x0, bb[0]);
        p1 = fmaf(W[5],  x0, bb[1]);
        p2 = fmaf(W[10], x0, bb[2]);
        p3 = fmaf(W[15], x0, bb[3]);
    }

    if (g == 0) {
        float l = bh[0];
        l = fmaf(Wh[0], h0, l);
        l = fmaf(Wh[1], h1, l);
        l = fmaf(Wh[2], h2, l);
        l = fmaf(Wh[3], h3, l);
        out_logits[b] = l;
    }
}

// ---------------------------------------------------------------------------
// Launch
// ---------------------------------------------------------------------------
extern "C" void kernel_launch(void* const* d_in, const int* in_sizes, int n_in,
                              void* d_out, int out_size) {
    const float* x   = (const float*)d_in[0];   // (16,128,8)
    const float* qw  = (const float*)d_in[1];   // (42,)
    const float* thf = (const float*)d_in[2];
    const float* thi = (const float*)d_in[3];
    const float* thg = (const float*)d_in[4];
    const float* tho = (const float*)d_in[5];
    const float* Wf  = (const float*)d_in[6];
    const float* bf  = (const float*)d_in[7];
    const float* Wi  = (const float*)d_in[8];
    const float* bi  = (const float*)d_in[9];
    const float* Wg  = (const float*)d_in[10];
    const float* bg  = (const float*)d_in[11];
    const float* Wo  = (const float*)d_in[12];
    const float* bo  = (const float*)d_in[13];
    const float* Wh  = (const float*)d_in[14];
    const float* bh  = (const float*)d_in[15];

    float* out = (float*)d_out;   // [0:2048] qcnn_out, [2048:2064] logits

    qcnn_kernel<<<16, 128>>>(x, qw, out);
    lstm_kernel<<<1, 64>>>(out, thf, thi, thg, tho,
                           Wf, bf, Wi, bi, Wg, bg, Wo, bo, Wh, bh,
                           out + 2048);
}

// round 9
// speedup vs baseline: 1.8214x; 1.0865x over previous
#include <cuda_runtime.h>
#include <math.h>

// ---------------------------------------------------------------------------
// helpers
// ---------------------------------------------------------------------------
__device__ __forceinline__ float2 cmul(float2 a, float2 b) {
    return make_float2(a.x * b.x - a.y * b.y, a.x * b.y + a.y * b.x);
}
__device__ __forceinline__ float ftanh(float x) {
    float r; asm("tanh.approx.f32 %0, %1;" : "=f"(r) : "f"(x)); return r;
}

// ---------------------------------------------------------------------------
// QCNN per-sample evaluation (4-amplitude sim of the (6,7) subsystem).
// Circuit factorizes over qubit pairs; Z_7 depends only on qubits 6,7.
// Relevant params: w[9:12] (conv pair (6,7)), w[21:24] (pool pair (6,7)).
// ---------------------------------------------------------------------------
__device__ __forceinline__ float qcnn_eval(const float* __restrict__ x,
                                           int i,
                                           float w9, float w10, float w11,
                                           float w21, float w22, float w23) {
    float2 q6a0, q6a1, q7a0, q7a1;
    {
        float ph = 2.0f * x[i * 8 + 6];
        float sp, cp; __sincosf(ph, &sp, &cp);
        q6a0 = make_float2(0.5f * (1.0f + cp), 0.5f * sp);
        float2 t = make_float2(0.5f * (1.0f - cp), -0.5f * sp);
        q6a1 = make_float2(cp * t.x - sp * t.y, cp * t.y + sp * t.x);
    }
    {
        float ph = 2.0f * x[i * 8 + 7];
        float sp, cp; __sincosf(ph, &sp, &cp);
        q7a0 = make_float2(0.5f * (1.0f + cp), 0.5f * sp);
        float2 t = make_float2(0.5f * (1.0f - cp), -0.5f * sp);
        q7a1 = make_float2(cp * t.x - sp * t.y, cp * t.y + sp * t.x);
    }

    float2 s00 = cmul(q6a0, q7a0);
    float2 s01 = cmul(q6a0, q7a1);
    float2 s10 = cmul(q6a1, q7a0);
    float2 s11 = cmul(q6a1, q7a1);

    const float R = 0.70710678118654752f;
    const float2 ePp = make_float2(R,  R);   // e^{+i pi/4}
    const float2 ePm = make_float2(R, -R);   // e^{-i pi/4}

    // ---- conv_block(w[9:12], q1=6, q2=7) ----
    s00 = cmul(s00, ePp); s10 = cmul(s10, ePp);
    s01 = cmul(s01, ePm); s11 = cmul(s11, ePm);
    { float2 t = s01; s01 = s11; s11 = t; }            // CX(7,6)
    {
        float hs, hc; __sincosf(0.5f * w9, &hs, &hc);  // RZ(w9) q6
        float2 em = make_float2(hc, -hs), ep = make_float2(hc, hs);
        s00 = cmul(s00, em); s01 = cmul(s01, em);
        s10 = cmul(s10, ep); s11 = cmul(s11, ep);
    }
    {
        float hs, hc; __sincosf(0.5f * w10, &hs, &hc); // RY(w10) q7
        float2 u = s00, v = s01;
        s00 = make_float2(hc * u.x - hs * v.x, hc * u.y - hs * v.y);
        s01 = make_float2(hs * u.x + hc * v.x, hs * u.y + hc * v.y);
        u = s10; v = s11;
        s10 = make_float2(hc * u.x - hs * v.x, hc * u.y - hs * v.y);
        s11 = make_float2(hs * u.x + hc * v.x, hs * u.y + hc * v.y);
    }
    { float2 t = s10; s10 = s11; s11 = t; }            // CX(6,7)
    {
        float hs, hc; __sincosf(0.5f * w11, &hs, &hc); // RY(w11) q7
        float2 u = s00, v = s01;
        s00 = make_float2(hc * u.x - hs * v.x, hc * u.y - hs * v.y);
        s01 = make_float2(hs * u.x + hc * v.x, hs * u.y + hc * v.y);
        u = s10; v = s11;
        s10 = make_float2(hc * u.x - hs * v.x, hc * u.y - hs * v.y);
        s11 = make_float2(hs * u.x + hc * v.x, hs * u.y + hc * v.y);
    }
    { float2 t = s01; s01 = s11; s11 = t; }            // CX(7,6)
    s00 = cmul(s00, ePm); s01 = cmul(s01, ePm);        // RZ(pi/2) q6
    s10 = cmul(s10, ePp); s11 = cmul(s11, ePp);

    // ---- pool_block(w[21:24], src=6, sink=7) ----
    s00 = cmul(s00, ePp); s10 = cmul(s10, ePp);
    s01 = cmul(s01, ePm); s11 = cmul(s11, ePm);
    { float2 t = s01; s01 = s11; s11 = t; }            // CX(7,6)
    {
        float hs, hc; __sincosf(0.5f * w21, &hs, &hc); // RZ(w21) q6
        float2 em = make_float2(hc, -hs), ep = make_float2(hc, hs);
        s00 = cmul(s00, em); s01 = cmul(s01, em);
        s10 = cmul(s10, ep); s11 = cmul(s11, ep);
    }
    {
        float hs, hc; __sincosf(0.5f * w22, &hs, &hc); // RY(w22) q7
        float2 u = s00, v = s01;
        s00 = make_float2(hc * u.x - hs * v.x, hc * u.y - hs * v.y);
        s01 = make_float2(hs * u.x + hc * v.x, hs * u.y + hc * v.y);
        u = s10; v = s11;
        s10 = make_float2(hc * u.x - hs * v.x, hc * u.y - hs * v.y);
        s11 = make_float2(hs * u.x + hc * v.x, hs * u.y + hc * v.y);
    }
    { float2 t = s10; s10 = s11; s11 = t; }            // CX(6,7)
    {
        float hs, hc; __sincosf(0.5f * w23, &hs, &hc); // RY(w23) q7
        float2 u = s00, v = s01;
        s00 = make_float2(hc * u.x - hs * v.x, hc * u.y - hs * v.y);
        s01 = make_float2(hs * u.x + hc * v.x, hs * u.y + hc * v.y);
        u = s10; v = s11;
        s10 = make_float2(hc * u.x - hs * v.x, hc * u.y - hs * v.y);
        s11 = make_float2(hs * u.x + hc * v.x, hs * u.y + hc * v.y);
    }

    return (s00.x * s00.x + s00.y * s00.y) + (s10.x * s10.x + s10.y * s10.y)
         - (s01.x * s01.x + s01.y * s01.y) - (s11.x * s11.x + s11.y * s11.y);
}

// ---------------------------------------------------------------------------
// Fused kernel: 1 block x 512 threads.
// Phase 1: all warps compute the 2048 qcnn values (4/thread) -> d_out + smem.
// Phase 2: threads 0..63 run the QLSTM (warp-synchronous, x from smem).
//   qgate closed form: c_i = cos(v_i + theta_i);
//   qgate = [c1c2c3, c0c1, c0c1c2, c0c1c2c3].
//   thread t<64: batch b = t>>2, gate g = t&3 (4-lane groups in-warp).
//   One-shot rotated transpose; sigmoid-type lanes (g != 2) pre-scale their
//   published z's by 0.5 inside the product tree, so receivers apply
//   tanh.approx directly: sig(x) = 0.5*tanh(0.5x)+0.5.
// ---------------------------------------------------------------------------
__global__ __launch_bounds__(512, 1)
void fused_kernel(const float* __restrict__ x,
                  const float* __restrict__ qw,
                  const float* __restrict__ thf, const float* __restrict__ thi,
                  const float* __restrict__ thg, const float* __restrict__ tho,
                  const float* __restrict__ Wf, const float* __restrict__ bf,
                  const float* __restrict__ Wi, const float* __restrict__ bi,
                  const float* __restrict__ Wg, const float* __restrict__ bg,
                  const float* __restrict__ Wo, const float* __restrict__ bo,
                  const float* __restrict__ Wh, const float* __restrict__ bh,
                  float* __restrict__ out) {
    __shared__ float xs[2048];           // qcnn outputs, (B=16, S=128)

    const unsigned FULL = 0xffffffffu;
    int tid = threadIdx.x;

    // ---------------- Phase 1: QCNN ----------------
    {
        float w9 = qw[9], w10 = qw[10], w11 = qw[11];
        float w21 = qw[21], w22 = qw[22], w23 = qw[23];
#pragma unroll
        for (int k = 0; k < 4; k++) {
            int i = tid + k * 512;
            float z = qcnn_eval(x, i, w9, w10, w11, w21, w22, w23);
            out[i] = z;
            xs[i] = z;
        }
    }
    __syncthreads();

    // ---------------- Phase 2: QLSTM (threads 0..63) ----------------
    if (tid < 64) {
        int b = tid >> 2;
        int g = tid & 3;
        int lane = tid & 31;
        int base = lane & ~3;
        bool g1 = (g & 1) != 0;
        bool g2b = (g & 2) != 0;

        int sl1 = base + ((g + 1) & 3);
        int sl2 = base + ((g + 2) & 3);
        int sl3 = base + ((g + 3) & 3);

        const float* Wsel = (g == 0) ? Wf : (g == 1) ? Wi : (g == 2) ? Wg : Wo;
        const float* bsel = (g == 0) ? bf : (g == 1) ? bi : (g == 2) ? bg : bo;
        const float* tsel = (g == 0) ? thf : (g == 1) ? thi : (g == 2) ? thg : tho;

        float W[20], bb[4];
#pragma unroll
        for (int k = 0; k < 20; k++) W[k] = Wsel[k];
#pragma unroll
        for (int k = 0; k < 4; k++) bb[k] = bsel[k] + tsel[k];

        // sigmoid-type gates pre-scale their published z's by 0.5
        float m = (g == 2) ? 1.0f : 0.5f;

        float h0 = 0.f, h1 = 0.f, h2 = 0.f, h3 = 0.f;
        float cm = 0.f;

        const float* xp = xs + b * 128;
        float x0 = xp[0];
        float p0 = fmaf(W[0],  x0, bb[0]);
        float p1 = fmaf(W[5],  x0, bb[1]);
        float p2 = fmaf(W[10], x0, bb[2]);
        float p3 = fmaf(W[15], x0, bb[3]);

#pragma unroll 2
        for (int s = 0; s < 128; s++) {
            float xn = xp[(s < 127) ? (s + 1) : 127];   // smem prefetch

            float ci0, ci1, ci2, ci3;
            {
                float m0 = W[2]  * h1, m1 = W[7]  * h1, m2 = W[12] * h1, m3 = W[17] * h1;
                float q0 = fmaf(W[1],  h0, p0), q1 = fmaf(W[6],  h0, p1);
                float q2 = fmaf(W[11], h0, p2), q3 = fmaf(W[16], h0, p3);
                float u0 = fmaf(W[3],  h2, m0), u1 = fmaf(W[8],  h2, m1);
                float u2 = fmaf(W[13], h2, m2), u3 = fmaf(W[18], h2, m3);
                ci0 = __cosf(fmaf(W[4],  h3, q0) + u0);
                ci1 = __cosf(fmaf(W[9],  h3, q1) + u1);
                ci2 = __cosf(fmaf(W[14], h3, q2) + u2);
                ci3 = __cosf(fmaf(W[19], h3, q3) + u3);
            }

            // scaled qgate outputs: each z carries exactly one factor of m
            float c23  = ci2 * ci3;
            float ci0m = m * ci0;
            float ci1m = m * ci1;
            float z1   = ci0m * ci1;     // m * c0*c1
            float z0   = ci1m * c23;     // m * c1*c2*c3
            float z2   = z1 * ci2;       // m * c0*c1*c2
            float z3   = z1 * c23;       // m * c0*c1*c2*c3

            // balanced depth-2 selects: pub_r = z[(g-r)&3], zg = z[g]
            float pub1 = g2b ? (g1 ? z2 : z1) : (g1 ? z0 : z3);
            float pub2 = g2b ? (g1 ? z1 : z0) : (g1 ? z3 : z2);
            float pub3 = g2b ? (g1 ? z0 : z3) : (g1 ? z2 : z1);
            float zg   = g2b ? (g1 ? z3 : z2) : (g1 ? z1 : z0);

            float r1 = __shfl_sync(FULL, pub1, sl1);  // gate (g+1)&3's z[g]
            float r2 = __shfl_sync(FULL, pub2, sl2);  // gate (g+2)&3's z[g]
            float r3 = __shfl_sync(FULL, pub3, sl3);  // gate (g+3)&3's z[g]

            // a_k = gate k's z[g] (a0,a1,a3 pre-scaled by 0.5; a2 unscaled)
            float a0 = g2b ? (g1 ? r1 : r2) : (g1 ? r3 : zg);
            float a1 = g2b ? (g1 ? r2 : r3) : (g1 ? zg : r1);
            float a2 = g2b ? (g1 ? r3 : zg) : (g1 ? r1 : r2);
            float a3 = g2b ? (g1 ? zg : r1) : (g1 ? r2 : r3);

            // sig(x) = 0.5*tanh(0.5x)+0.5; inputs a0,a1,a3 already halved
            float fv = fmaf(0.5f, ftanh(a0), 0.5f);
            float iv = fmaf(0.5f, ftanh(a1), 0.5f);
            float gv = ftanh(a2);
            float ov = fmaf(0.5f, ftanh(a3), 0.5f);

            float cn = fmaf(fv, cm, iv * gv);
            cm = cn;
            float hm = ov * ftanh(cn);

            h0 = __shfl_sync(FULL, hm, base + 0);
            h1 = __shfl_sync(FULL, hm, base + 1);
            h2 = __shfl_sync(FULL, hm, base + 2);
            h3 = __shfl_sync(FULL, hm, base + 3);

            x0 = xn;
            p0 = fmaf(W[0],  x0, bb[0]);
            p1 = fmaf(W[5],  x0, bb[1]);
            p2 = fmaf(W[10], x0, bb[2]);
            p3 = fmaf(W[15], x0, bb[3]);
        }

        if (g == 0) {
            float l = bh[0];
            l = fmaf(Wh[0], h0, l);
            l = fmaf(Wh[1], h1, l);
            l = fmaf(Wh[2], h2, l);
            l = fmaf(Wh[3], h3, l);
            out[2048 + b] = l;
        }
    }
}

// ---------------------------------------------------------------------------
// Launch
// ---------------------------------------------------------------------------
extern "C" void kernel_launch(void* const* d_in, const int* in_sizes, int n_in,
                              void* d_out, int out_size) {
    const float* x   = (const float*)d_in[0];   // (16,128,8)
    const float* qw  = (const float*)d_in[1];   // (42,)
    const float* thf = (const float*)d_in[2];
    const float* thi = (const float*)d_in[3];
    const float* thg = (const float*)d_in[4];
    const float* tho = (const float*)d_in[5];
    const float* Wf  = (const float*)d_in[6];
    const float* bf  = (const float*)d_in[7];
    const float* Wi  = (const float*)d_in[8];
    const float* bi  = (const float*)d_in[9];
    const float* Wg  = (const float*)d_in[10];
    const float* bg  = (const float*)d_in[11];
    const float* Wo  = (const float*)d_in[12];
    const float* bo  = (const float*)d_in[13];
    const float* Wh  = (const float*)d_in[14];
    const float* bh  = (const float*)d_in[15];

    float* out = (float*)d_out;   // [0:2048] qcnn_out, [2048:2064] logits

    fused_kernel<<<1, 512>>>(x, qw, thf, thi, thg, tho,
                             Wf, bf, Wi, bi, Wg, bg, Wo, bo, Wh, bh, out);
}